// round 3
// baseline (speedup 1.0000x reference)
#include <cuda_runtime.h>
#include <cuda_bf16.h>
#include <math.h>

// Problem constants
#define BATCH   2
#define SEQ     1024
#define DMODEL  2048
#define NHEAD   32
#define NKVHEAD 8
#define DK      64
#define KVDIM   (NKVHEAD * DK)   // 512
#define NTOK    (BATCH * SEQ)    // 2048

// ---------------------------------------------------------------------------
// Scratch buffers (no allocation allowed -> __device__ globals)
// ---------------------------------------------------------------------------
__device__ float g_Q[NTOK * DMODEL];   // 16 MB
__device__ float g_K[NTOK * KVDIM];    //  4 MB
__device__ float g_V[NTOK * KVDIM];    //  4 MB
__device__ float g_O[NTOK * DMODEL];   // 16 MB

// ---------------------------------------------------------------------------
// SGEMM with bias: C[M,N] = A[M,K] @ W[K,N] + bias[N]
// BM=BN=128, BK=16, 256 threads, 8x8 register tile.
// Requires M%128==0, N%128==0, K%16==0 (true for all our shapes).
// ---------------------------------------------------------------------------
__global__ __launch_bounds__(256, 2)
void sgemm_bias_kernel(const float* __restrict__ A,
                       const float* __restrict__ W,
                       const float* __restrict__ bias,
                       float* __restrict__ C,
                       int M, int N, int K)
{
    __shared__ float As[16][128];
    __shared__ float Bs[16][128];

    const int tid = threadIdx.x;
    const int bm = blockIdx.y * 128;
    const int bn = blockIdx.x * 128;
    const int tx = tid & 15;   // 0..15 -> cols tx*8
    const int ty = tid >> 4;   // 0..15 -> rows ty*8

    float acc[8][8];
#pragma unroll
    for (int i = 0; i < 8; i++)
#pragma unroll
        for (int j = 0; j < 8; j++) acc[i][j] = 0.f;

    for (int k0 = 0; k0 < K; k0 += 16) {
        // Load A tile (128x16) transposed into As[16][128]
#pragma unroll
        for (int t = 0; t < 2; t++) {
            int id  = tid + t * 256;      // 0..511 float4 ids
            int row = id >> 2;            // 0..127
            int c4  = id & 3;             // 0..3
            float4 v = *(const float4*)&A[(size_t)(bm + row) * K + k0 + c4 * 4];
            As[c4 * 4 + 0][row] = v.x;
            As[c4 * 4 + 1][row] = v.y;
            As[c4 * 4 + 2][row] = v.z;
            As[c4 * 4 + 3][row] = v.w;
        }
        // Load W tile (16x128)
#pragma unroll
        for (int t = 0; t < 2; t++) {
            int id  = tid + t * 256;
            int row = id >> 5;            // 0..15
            int c4  = id & 31;            // 0..31
            *(float4*)&Bs[row][c4 * 4] =
                *(const float4*)&W[(size_t)(k0 + row) * N + bn + c4 * 4];
        }
        __syncthreads();

#pragma unroll
        for (int k = 0; k < 16; k++) {
            float a[8], b[8];
            *(float4*)&a[0] = *(const float4*)&As[k][ty * 8];
            *(float4*)&a[4] = *(const float4*)&As[k][ty * 8 + 4];
            *(float4*)&b[0] = *(const float4*)&Bs[k][tx * 8];
            *(float4*)&b[4] = *(const float4*)&Bs[k][tx * 8 + 4];
#pragma unroll
            for (int i = 0; i < 8; i++)
#pragma unroll
                for (int j = 0; j < 8; j++)
                    acc[i][j] = fmaf(a[i], b[j], acc[i][j]);
        }
        __syncthreads();
    }

    // Epilogue with bias
#pragma unroll
    for (int i = 0; i < 8; i++) {
        int row = bm + ty * 8 + i;
#pragma unroll
        for (int j4 = 0; j4 < 2; j4++) {
            int col = bn + tx * 8 + j4 * 4;
            float4 bv = *(const float4*)&bias[col];
            float4 o;
            o.x = acc[i][j4 * 4 + 0] + bv.x;
            o.y = acc[i][j4 * 4 + 1] + bv.y;
            o.z = acc[i][j4 * 4 + 2] + bv.z;
            o.w = acc[i][j4 * 4 + 3] + bv.w;
            *(float4*)&C[(size_t)row * N + col] = o;
        }
    }
}

// ---------------------------------------------------------------------------
// RoPE (in-place). T: [NTOK, ncols], heads of 64, pairs (2i, 2i+1), half=32.
// pos = token % SEQ. inv_freq = 10000^(-i/32).
// ---------------------------------------------------------------------------
__global__ void rope_kernel(float* __restrict__ T, int ncols)
{
    int idx = blockIdx.x * blockDim.x + threadIdx.x;
    int npairs_row = ncols >> 1;
    int total = NTOK * npairs_row;
    if (idx >= total) return;
    int t = idx / npairs_row;
    int p = idx - t * npairs_row;
    int i = p & 31;                       // within-head pair index (half = 32)
    int pos = t & (SEQ - 1);

    float inv = __powf(10000.0f, -(float)i / 32.0f);
    float ang = (float)pos * inv;
    float s, c;
    sincosf(ang, &s, &c);

    float* base = T + (size_t)t * ncols + 2 * p;
    float e = base[0];
    float o = base[1];
    base[0] = e * c - o * s;
    base[1] = e * s + o * c;
}

// ---------------------------------------------------------------------------
// Flash attention (causal, GQA). One block per (q_tile, b*h).
// BM = BN = 64, d = 64, 256 threads, 4x4 register tiles, online softmax.
// Dynamic smem layout (floats):
//   Qs[64*64] Ks[64*68] Vs[64*64] Ss[64*68] rm[64] rl[64] rs[64]
// ---------------------------------------------------------------------------
#define ATTN_SMEM_FLOATS (64*64 + 64*68 + 64*64 + 64*68 + 3*64)
#define ATTN_SMEM_BYTES  (ATTN_SMEM_FLOATS * 4)

__global__ __launch_bounds__(256)
void attention_kernel(const float* __restrict__ Q,
                      const float* __restrict__ K,
                      const float* __restrict__ V,
                      float* __restrict__ O)
{
    extern __shared__ float sm[];
    float* Qs = sm;                  // [64][64]
    float* Ks = Qs + 64 * 64;        // [64][68] padded
    float* Vs = Ks + 64 * 68;        // [64][64]
    float* Ss = Vs + 64 * 64;        // [64][68] padded
    float* rm = Ss + 64 * 68;        // [64]
    float* rl = rm + 64;             // [64]
    float* rs = rl + 64;             // [64]

    const int tid = threadIdx.x;
    const int tx = tid & 15;         // cols tx*4..tx*4+3
    const int ty = tid >> 4;         // rows ty*4..ty*4+3

    const int qt = blockIdx.x;       // q tile (0..15)
    const int bh = blockIdx.y;       // 0..63
    const int b  = bh >> 5;          // /NHEAD
    const int h  = bh & 31;
    const int g  = h >> 2;           // kv head = h / (NHEAD/NKVHEAD)

    const float* Qbase = Q + (size_t)(b * SEQ) * DMODEL + h * DK;
    const float* Kbase = K + (size_t)(b * SEQ) * KVDIM + g * DK;
    const float* Vbase = V + (size_t)(b * SEQ) * KVDIM + g * DK;
    float*       Obase = O + (size_t)(b * SEQ) * DMODEL + h * DK;

    // Load Q tile (scaled by 1/sqrt(dk) = 0.125)
#pragma unroll
    for (int t = 0; t < 4; t++) {
        int id = tid + t * 256;          // 0..1023 float4 ids
        int r  = id >> 4;                // 0..63
        int c4 = id & 15;                // 0..15
        float4 v = *(const float4*)&Qbase[(size_t)(qt * 64 + r) * DMODEL + c4 * 4];
        v.x *= 0.125f; v.y *= 0.125f; v.z *= 0.125f; v.w *= 0.125f;
        *(float4*)&Qs[r * 64 + c4 * 4] = v;
    }
    if (tid < 64) { rm[tid] = -1e30f; rl[tid] = 0.f; }

    float o[4][4];
#pragma unroll
    for (int i = 0; i < 4; i++)
#pragma unroll
        for (int j = 0; j < 4; j++) o[i][j] = 0.f;

    __syncthreads();

    for (int jt = 0; jt <= qt; jt++) {
        // Load K, V tiles
#pragma unroll
        for (int t = 0; t < 4; t++) {
            int id = tid + t * 256;
            int r  = id >> 4;
            int c4 = id & 15;
            float4 kv = *(const float4*)&Kbase[(size_t)(jt * 64 + r) * KVDIM + c4 * 4];
            *(float4*)&Ks[r * 68 + c4 * 4] = kv;
            float4 vv = *(const float4*)&Vbase[(size_t)(jt * 64 + r) * KVDIM + c4 * 4];
            *(float4*)&Vs[r * 64 + c4 * 4] = vv;
        }
        __syncthreads();

        // S = Q K^T (4x4 per thread)
        float s[4][4];
#pragma unroll
        for (int i = 0; i < 4; i++)
#pragma unroll
            for (int j = 0; j < 4; j++) s[i][j] = 0.f;

#pragma unroll
        for (int d4 = 0; d4 < 16; d4++) {
            float4 q4[4], k4[4];
#pragma unroll
            for (int i = 0; i < 4; i++)
                q4[i] = *(const float4*)&Qs[(ty * 4 + i) * 64 + d4 * 4];
#pragma unroll
            for (int j = 0; j < 4; j++)
                k4[j] = *(const float4*)&Ks[(tx * 4 + j) * 68 + d4 * 4];
#pragma unroll
            for (int i = 0; i < 4; i++)
#pragma unroll
                for (int j = 0; j < 4; j++) {
                    s[i][j] = fmaf(q4[i].x, k4[j].x, s[i][j]);
                    s[i][j] = fmaf(q4[i].y, k4[j].y, s[i][j]);
                    s[i][j] = fmaf(q4[i].z, k4[j].z, s[i][j]);
                    s[i][j] = fmaf(q4[i].w, k4[j].w, s[i][j]);
                }
        }

        // Causal mask on diagonal tile, write S to shared
        if (jt == qt) {
#pragma unroll
            for (int i = 0; i < 4; i++) {
                int qr = ty * 4 + i;
#pragma unroll
                for (int j = 0; j < 4; j++) {
                    int kc = tx * 4 + j;
                    if (kc > qr) s[i][j] = -1e30f;
                }
            }
        }
#pragma unroll
        for (int i = 0; i < 4; i++) {
            float4 sv = make_float4(s[i][0], s[i][1], s[i][2], s[i][3]);
            *(float4*)&Ss[(ty * 4 + i) * 68 + tx * 4] = sv;
        }
        __syncthreads();

        // Online softmax: one thread per row
        if (tid < 64) {
            float* srow = &Ss[tid * 68];
            float mloc = -1e30f;
#pragma unroll 8
            for (int c = 0; c < 64; c++) mloc = fmaxf(mloc, srow[c]);
            float mold = rm[tid];
            float mnew = fmaxf(mold, mloc);
            float scale = __expf(mold - mnew);
            float lnew = rl[tid] * scale;
#pragma unroll 8
            for (int c = 0; c < 64; c++) {
                float p = __expf(srow[c] - mnew);
                srow[c] = p;
                lnew += p;
            }
            rm[tid] = mnew;
            rl[tid] = lnew;
            rs[tid] = scale;
        }
        __syncthreads();

        // Rescale O and accumulate O += P @ V
        float sc[4];
#pragma unroll
        for (int i = 0; i < 4; i++) sc[i] = rs[ty * 4 + i];
#pragma unroll
        for (int i = 0; i < 4; i++)
#pragma unroll
            for (int j = 0; j < 4; j++) o[i][j] *= sc[i];

#pragma unroll 4
        for (int k = 0; k < 64; k++) {
            float4 v4 = *(const float4*)&Vs[k * 64 + tx * 4];
            float p0 = Ss[(ty * 4 + 0) * 68 + k];
            float p1 = Ss[(ty * 4 + 1) * 68 + k];
            float p2 = Ss[(ty * 4 + 2) * 68 + k];
            float p3 = Ss[(ty * 4 + 3) * 68 + k];
            o[0][0] = fmaf(p0, v4.x, o[0][0]); o[0][1] = fmaf(p0, v4.y, o[0][1]);
            o[0][2] = fmaf(p0, v4.z, o[0][2]); o[0][3] = fmaf(p0, v4.w, o[0][3]);
            o[1][0] = fmaf(p1, v4.x, o[1][0]); o[1][1] = fmaf(p1, v4.y, o[1][1]);
            o[1][2] = fmaf(p1, v4.z, o[1][2]); o[1][3] = fmaf(p1, v4.w, o[1][3]);
            o[2][0] = fmaf(p2, v4.x, o[2][0]); o[2][1] = fmaf(p2, v4.y, o[2][1]);
            o[2][2] = fmaf(p2, v4.z, o[2][2]); o[2][3] = fmaf(p2, v4.w, o[2][3]);
            o[3][0] = fmaf(p3, v4.x, o[3][0]); o[3][1] = fmaf(p3, v4.y, o[3][1]);
            o[3][2] = fmaf(p3, v4.z, o[3][2]); o[3][3] = fmaf(p3, v4.w, o[3][3]);
        }
        __syncthreads();
    }

    // Normalize and write out
#pragma unroll
    for (int i = 0; i < 4; i++) {
        float linv = 1.0f / rl[ty * 4 + i];
        float4 ov = make_float4(o[i][0] * linv, o[i][1] * linv,
                                o[i][2] * linv, o[i][3] * linv);
        *(float4*)&Obase[(size_t)(qt * 64 + ty * 4 + i) * DMODEL + tx * 4] = ov;
    }
}

// ---------------------------------------------------------------------------
// Launch
// ---------------------------------------------------------------------------
extern "C" void kernel_launch(void* const* d_in, const int* in_sizes, int n_in,
                              void* d_out, int out_size)
{
    const float* x  = (const float*)d_in[0];
    const float* Wq = (const float*)d_in[1];
    const float* bq = (const float*)d_in[2];
    const float* Wk = (const float*)d_in[3];
    const float* bk = (const float*)d_in[4];
    const float* Wv = (const float*)d_in[5];
    const float* bv = (const float*)d_in[6];
    const float* Wo = (const float*)d_in[7];
    const float* bo = (const float*)d_in[8];
    float* out = (float*)d_out;

    float *Qb, *Kb, *Vb, *Ob;
    cudaGetSymbolAddress((void**)&Qb, g_Q);
    cudaGetSymbolAddress((void**)&Kb, g_K);
    cudaGetSymbolAddress((void**)&Vb, g_V);
    cudaGetSymbolAddress((void**)&Ob, g_O);

    // QKV projections
    {
        dim3 grid(DMODEL / 128, NTOK / 128);
        sgemm_bias_kernel<<<grid, 256>>>(x, Wq, bq, Qb, NTOK, DMODEL, DMODEL);
    }
    {
        dim3 grid(KVDIM / 128, NTOK / 128);
        sgemm_bias_kernel<<<grid, 256>>>(x, Wk, bk, Kb, NTOK, KVDIM, DMODEL);
        sgemm_bias_kernel<<<grid, 256>>>(x, Wv, bv, Vb, NTOK, KVDIM, DMODEL);
    }

    // RoPE on Q and K
    {
        int totalQ = NTOK * (DMODEL / 2);
        rope_kernel<<<(totalQ + 255) / 256, 256>>>(Qb, DMODEL);
        int totalK = NTOK * (KVDIM / 2);
        rope_kernel<<<(totalK + 255) / 256, 256>>>(Kb, KVDIM);
    }

    // Attention
    {
        cudaFuncSetAttribute(attention_kernel,
                             cudaFuncAttributeMaxDynamicSharedMemorySize,
                             ATTN_SMEM_BYTES);
        dim3 grid(SEQ / 64, BATCH * NHEAD);
        attention_kernel<<<grid, 256, ATTN_SMEM_BYTES>>>(Qb, Kb, Vb, Ob);
    }

    // Output projection
    {
        dim3 grid(DMODEL / 128, NTOK / 128);
        sgemm_bias_kernel<<<grid, 256>>>(Ob, Wo, bo, out, NTOK, DMODEL, DMODEL);
    }
}

// round 4
// speedup vs baseline: 2.2533x; 2.2533x over previous
#include <cuda_runtime.h>
#include <cuda_bf16.h>
#include <math.h>

// Problem constants
#define BATCH   2
#define SEQ     1024
#define DMODEL  2048
#define NHEAD   32
#define NKVHEAD 8
#define DK      64
#define KVDIM   (NKVHEAD * DK)   // 512
#define NTOK    (BATCH * SEQ)    // 2048

// ---------------------------------------------------------------------------
// Scratch buffers
// ---------------------------------------------------------------------------
__device__ float g_Q[NTOK * DMODEL];   // 16 MB
__device__ float g_K[NTOK * KVDIM];    //  4 MB
__device__ float g_V[NTOK * KVDIM];    //  4 MB
__device__ float g_O[NTOK * DMODEL];   // 16 MB

// ---------------------------------------------------------------------------
// tf32 helpers
// ---------------------------------------------------------------------------
__device__ __forceinline__ float to_tf32(float x)
{
    unsigned u;
    asm volatile("cvt.rna.tf32.f32 %0, %1;\n" : "=r"(u) : "f"(x));
    return __uint_as_float(u);
}

__device__ __forceinline__ void mma_tf32_16x8x8(float d[4],
                                                const float a[4],
                                                const float b[2])
{
    asm volatile(
        "mma.sync.aligned.m16n8k8.row.col.f32.tf32.tf32.f32 "
        "{%0,%1,%2,%3}, {%4,%5,%6,%7}, {%8,%9}, {%0,%1,%2,%3};\n"
        : "+f"(d[0]), "+f"(d[1]), "+f"(d[2]), "+f"(d[3])
        : "r"(__float_as_uint(a[0])), "r"(__float_as_uint(a[1])),
          "r"(__float_as_uint(a[2])), "r"(__float_as_uint(a[3])),
          "r"(__float_as_uint(b[0])), "r"(__float_as_uint(b[1])));
}

// ---------------------------------------------------------------------------
// TF32 tensor-core GEMM with bias: C[M,N] = A[M,K] @ W[K,N] + bias[N]
// BM=BN=128, BK=32, 256 threads (8 warps), warp tile 32x64.
// Requires M%128==0, N%128==0, K%32==0.
// Fragment layouts per PTX m16n8k8 tf32:
//   A a0: (grp, tig)  a1: (grp+8, tig)  a2: (grp, tig+4)  a3: (grp+8, tig+4)
//   B b0: (k=tig, n=grp)  b1: (k=tig+4, n=grp)
//   C c0/c1: (grp, tig*2 /+1)  c2/c3: (grp+8, tig*2 /+1)
// ---------------------------------------------------------------------------
__global__ __launch_bounds__(256, 2)
void tf32_gemm_bias_kernel(const float* __restrict__ A,
                           const float* __restrict__ W,
                           const float* __restrict__ bias,
                           float* __restrict__ C,
                           int M, int N, int K)
{
    __shared__ float As[128][36];   // [m][k], +4 pad
    __shared__ float Bs[128][36];   // [n][k], +4 pad (transposed)

    const int tid  = threadIdx.x;
    const int warp = tid >> 5;
    const int lane = tid & 31;
    const int wm   = warp & 3;      // 0..3 -> M offset wm*32
    const int wn   = warp >> 2;     // 0..1 -> N offset wn*64
    const int grp  = lane >> 2;     // 0..7
    const int tig  = lane & 3;      // 0..3

    const int bm = blockIdx.y * 128;
    const int bn = blockIdx.x * 128;

    float d[2][8][4];
#pragma unroll
    for (int mt = 0; mt < 2; mt++)
#pragma unroll
        for (int nt = 0; nt < 8; nt++)
#pragma unroll
            for (int i = 0; i < 4; i++) d[mt][nt][i] = 0.f;

    for (int k0 = 0; k0 < K; k0 += 32) {
        // Load A tile 128x32 (row-major, coalesced along K)
#pragma unroll
        for (int t = 0; t < 4; t++) {
            int id = tid + t * 256;       // 0..1023
            int r  = id >> 3;             // 0..127
            int c4 = id & 7;              // 0..7
            float4 v = *(const float4*)&A[(size_t)(bm + r) * K + k0 + c4 * 4];
            v.x = to_tf32(v.x); v.y = to_tf32(v.y);
            v.z = to_tf32(v.z); v.w = to_tf32(v.w);
            As[r][c4 * 4 + 0] = v.x;
            As[r][c4 * 4 + 1] = v.y;
            As[r][c4 * 4 + 2] = v.z;
            As[r][c4 * 4 + 3] = v.w;
        }
        // Load W tile 32x128, transpose into Bs[n][k]
#pragma unroll
        for (int t = 0; t < 4; t++) {
            int id = tid + t * 256;
            int r  = id >> 5;             // k row 0..31
            int c4 = id & 31;             // n/4  0..31
            float4 v = *(const float4*)&W[(size_t)(k0 + r) * N + bn + c4 * 4];
            Bs[c4 * 4 + 0][r] = to_tf32(v.x);
            Bs[c4 * 4 + 1][r] = to_tf32(v.y);
            Bs[c4 * 4 + 2][r] = to_tf32(v.z);
            Bs[c4 * 4 + 3][r] = to_tf32(v.w);
        }
        __syncthreads();

#pragma unroll
        for (int ks = 0; ks < 4; ks++) {
            const int kb = ks * 8;
            float a[2][4];
#pragma unroll
            for (int mt = 0; mt < 2; mt++) {
                int row = wm * 32 + mt * 16 + grp;
                a[mt][0] = As[row    ][kb + tig];
                a[mt][1] = As[row + 8][kb + tig];
                a[mt][2] = As[row    ][kb + tig + 4];
                a[mt][3] = As[row + 8][kb + tig + 4];
            }
#pragma unroll
            for (int nt = 0; nt < 8; nt++) {
                float b[2];
                int col = wn * 64 + nt * 8 + grp;
                b[0] = Bs[col][kb + tig];
                b[1] = Bs[col][kb + tig + 4];
#pragma unroll
                for (int mt = 0; mt < 2; mt++)
                    mma_tf32_16x8x8(d[mt][nt], a[mt], b);
            }
        }
        __syncthreads();
    }

    // Epilogue: bias + store (float2 per fragment row)
#pragma unroll
    for (int mt = 0; mt < 2; mt++) {
        int row0 = bm + wm * 32 + mt * 16 + grp;
#pragma unroll
        for (int nt = 0; nt < 8; nt++) {
            int col = bn + wn * 64 + nt * 8 + tig * 2;
            float2 bv = *(const float2*)&bias[col];
            float2 o0, o1;
            o0.x = d[mt][nt][0] + bv.x;  o0.y = d[mt][nt][1] + bv.y;
            o1.x = d[mt][nt][2] + bv.x;  o1.y = d[mt][nt][3] + bv.y;
            *(float2*)&C[(size_t)row0 * N + col]       = o0;
            *(float2*)&C[(size_t)(row0 + 8) * N + col] = o1;
        }
    }
}

// ---------------------------------------------------------------------------
// RoPE (in-place). T: [NTOK, ncols], heads of 64, pairs (2i, 2i+1), half=32.
// ---------------------------------------------------------------------------
__global__ void rope_kernel(float* __restrict__ T, int ncols)
{
    int idx = blockIdx.x * blockDim.x + threadIdx.x;
    int npairs_row = ncols >> 1;
    int total = NTOK * npairs_row;
    if (idx >= total) return;
    int t = idx / npairs_row;
    int p = idx - t * npairs_row;
    int i = p & 31;
    int pos = t & (SEQ - 1);

    float inv = __powf(10000.0f, -(float)i / 32.0f);
    float ang = (float)pos * inv;
    float s, c;
    sincosf(ang, &s, &c);

    float* base = T + (size_t)t * ncols + 2 * p;
    float e = base[0];
    float o = base[1];
    base[0] = e * c - o * s;
    base[1] = e * s + o * c;
}

// ---------------------------------------------------------------------------
// Flash attention (causal, GQA). One block per (q_tile, b*h). fp32.
// ---------------------------------------------------------------------------
#define ATTN_SMEM_FLOATS (64*64 + 64*68 + 64*64 + 64*68 + 3*64)
#define ATTN_SMEM_BYTES  (ATTN_SMEM_FLOATS * 4)

__global__ __launch_bounds__(256)
void attention_kernel(const float* __restrict__ Q,
                      const float* __restrict__ K,
                      const float* __restrict__ V,
                      float* __restrict__ O)
{
    extern __shared__ float sm[];
    float* Qs = sm;                  // [64][64]
    float* Ks = Qs + 64 * 64;        // [64][68]
    float* Vs = Ks + 64 * 68;        // [64][64]
    float* Ss = Vs + 64 * 64;        // [64][68]
    float* rm = Ss + 64 * 68;        // [64]
    float* rl = rm + 64;             // [64]
    float* rs = rl + 64;             // [64]

    const int tid = threadIdx.x;
    const int tx = tid & 15;
    const int ty = tid >> 4;

    const int qt = blockIdx.x;
    const int bh = blockIdx.y;
    const int b  = bh >> 5;
    const int h  = bh & 31;
    const int g  = h >> 2;

    const float* Qbase = Q + (size_t)(b * SEQ) * DMODEL + h * DK;
    const float* Kbase = K + (size_t)(b * SEQ) * KVDIM + g * DK;
    const float* Vbase = V + (size_t)(b * SEQ) * KVDIM + g * DK;
    float*       Obase = O + (size_t)(b * SEQ) * DMODEL + h * DK;

#pragma unroll
    for (int t = 0; t < 4; t++) {
        int id = tid + t * 256;
        int r  = id >> 4;
        int c4 = id & 15;
        float4 v = *(const float4*)&Qbase[(size_t)(qt * 64 + r) * DMODEL + c4 * 4];
        v.x *= 0.125f; v.y *= 0.125f; v.z *= 0.125f; v.w *= 0.125f;
        *(float4*)&Qs[r * 64 + c4 * 4] = v;
    }
    if (tid < 64) { rm[tid] = -1e30f; rl[tid] = 0.f; }

    float o[4][4];
#pragma unroll
    for (int i = 0; i < 4; i++)
#pragma unroll
        for (int j = 0; j < 4; j++) o[i][j] = 0.f;

    __syncthreads();

    for (int jt = 0; jt <= qt; jt++) {
#pragma unroll
        for (int t = 0; t < 4; t++) {
            int id = tid + t * 256;
            int r  = id >> 4;
            int c4 = id & 15;
            float4 kv = *(const float4*)&Kbase[(size_t)(jt * 64 + r) * KVDIM + c4 * 4];
            *(float4*)&Ks[r * 68 + c4 * 4] = kv;
            float4 vv = *(const float4*)&Vbase[(size_t)(jt * 64 + r) * KVDIM + c4 * 4];
            *(float4*)&Vs[r * 64 + c4 * 4] = vv;
        }
        __syncthreads();

        float s[4][4];
#pragma unroll
        for (int i = 0; i < 4; i++)
#pragma unroll
            for (int j = 0; j < 4; j++) s[i][j] = 0.f;

#pragma unroll
        for (int d4 = 0; d4 < 16; d4++) {
            float4 q4[4], k4[4];
#pragma unroll
            for (int i = 0; i < 4; i++)
                q4[i] = *(const float4*)&Qs[(ty * 4 + i) * 64 + d4 * 4];
#pragma unroll
            for (int j = 0; j < 4; j++)
                k4[j] = *(const float4*)&Ks[(tx * 4 + j) * 68 + d4 * 4];
#pragma unroll
            for (int i = 0; i < 4; i++)
#pragma unroll
                for (int j = 0; j < 4; j++) {
                    s[i][j] = fmaf(q4[i].x, k4[j].x, s[i][j]);
                    s[i][j] = fmaf(q4[i].y, k4[j].y, s[i][j]);
                    s[i][j] = fmaf(q4[i].z, k4[j].z, s[i][j]);
                    s[i][j] = fmaf(q4[i].w, k4[j].w, s[i][j]);
                }
        }

        if (jt == qt) {
#pragma unroll
            for (int i = 0; i < 4; i++) {
                int qr = ty * 4 + i;
#pragma unroll
                for (int j = 0; j < 4; j++) {
                    int kc = tx * 4 + j;
                    if (kc > qr) s[i][j] = -1e30f;
                }
            }
        }
#pragma unroll
        for (int i = 0; i < 4; i++) {
            float4 sv = make_float4(s[i][0], s[i][1], s[i][2], s[i][3]);
            *(float4*)&Ss[(ty * 4 + i) * 68 + tx * 4] = sv;
        }
        __syncthreads();

        if (tid < 64) {
            float* srow = &Ss[tid * 68];
            float mloc = -1e30f;
#pragma unroll 8
            for (int c = 0; c < 64; c++) mloc = fmaxf(mloc, srow[c]);
            float mold = rm[tid];
            float mnew = fmaxf(mold, mloc);
            float scale = __expf(mold - mnew);
            float lnew = rl[tid] * scale;
#pragma unroll 8
            for (int c = 0; c < 64; c++) {
                float p = __expf(srow[c] - mnew);
                srow[c] = p;
                lnew += p;
            }
            rm[tid] = mnew;
            rl[tid] = lnew;
            rs[tid] = scale;
        }
        __syncthreads();

        float sc[4];
#pragma unroll
        for (int i = 0; i < 4; i++) sc[i] = rs[ty * 4 + i];
#pragma unroll
        for (int i = 0; i < 4; i++)
#pragma unroll
            for (int j = 0; j < 4; j++) o[i][j] *= sc[i];

#pragma unroll 4
        for (int k = 0; k < 64; k++) {
            float4 v4 = *(const float4*)&Vs[k * 64 + tx * 4];
            float p0 = Ss[(ty * 4 + 0) * 68 + k];
            float p1 = Ss[(ty * 4 + 1) * 68 + k];
            float p2 = Ss[(ty * 4 + 2) * 68 + k];
            float p3 = Ss[(ty * 4 + 3) * 68 + k];
            o[0][0] = fmaf(p0, v4.x, o[0][0]); o[0][1] = fmaf(p0, v4.y, o[0][1]);
            o[0][2] = fmaf(p0, v4.z, o[0][2]); o[0][3] = fmaf(p0, v4.w, o[0][3]);
            o[1][0] = fmaf(p1, v4.x, o[1][0]); o[1][1] = fmaf(p1, v4.y, o[1][1]);
            o[1][2] = fmaf(p1, v4.z, o[1][2]); o[1][3] = fmaf(p1, v4.w, o[1][3]);
            o[2][0] = fmaf(p2, v4.x, o[2][0]); o[2][1] = fmaf(p2, v4.y, o[2][1]);
            o[2][2] = fmaf(p2, v4.z, o[2][2]); o[2][3] = fmaf(p2, v4.w, o[2][3]);
            o[3][0] = fmaf(p3, v4.x, o[3][0]); o[3][1] = fmaf(p3, v4.y, o[3][1]);
            o[3][2] = fmaf(p3, v4.z, o[3][2]); o[3][3] = fmaf(p3, v4.w, o[3][3]);
        }
        __syncthreads();
    }

#pragma unroll
    for (int i = 0; i < 4; i++) {
        float linv = 1.0f / rl[ty * 4 + i];
        float4 ov = make_float4(o[i][0] * linv, o[i][1] * linv,
                                o[i][2] * linv, o[i][3] * linv);
        *(float4*)&Obase[(size_t)(qt * 64 + ty * 4 + i) * DMODEL + tx * 4] = ov;
    }
}

// ---------------------------------------------------------------------------
// Launch
// ---------------------------------------------------------------------------
extern "C" void kernel_launch(void* const* d_in, const int* in_sizes, int n_in,
                              void* d_out, int out_size)
{
    const float* x  = (const float*)d_in[0];
    const float* Wq = (const float*)d_in[1];
    const float* bq = (const float*)d_in[2];
    const float* Wk = (const float*)d_in[3];
    const float* bk = (const float*)d_in[4];
    const float* Wv = (const float*)d_in[5];
    const float* bv = (const float*)d_in[6];
    const float* Wo = (const float*)d_in[7];
    const float* bo = (const float*)d_in[8];
    float* out = (float*)d_out;

    float *Qb, *Kb, *Vb, *Ob;
    cudaGetSymbolAddress((void**)&Qb, g_Q);
    cudaGetSymbolAddress((void**)&Kb, g_K);
    cudaGetSymbolAddress((void**)&Vb, g_V);
    cudaGetSymbolAddress((void**)&Ob, g_O);

    // QKV projections (tf32 tensor cores)
    {
        dim3 grid(DMODEL / 128, NTOK / 128);
        tf32_gemm_bias_kernel<<<grid, 256>>>(x, Wq, bq, Qb, NTOK, DMODEL, DMODEL);
    }
    {
        dim3 grid(KVDIM / 128, NTOK / 128);
        tf32_gemm_bias_kernel<<<grid, 256>>>(x, Wk, bk, Kb, NTOK, KVDIM, DMODEL);
        tf32_gemm_bias_kernel<<<grid, 256>>>(x, Wv, bv, Vb, NTOK, KVDIM, DMODEL);
    }

    // RoPE on Q and K
    {
        int totalQ = NTOK * (DMODEL / 2);
        rope_kernel<<<(totalQ + 255) / 256, 256>>>(Qb, DMODEL);
        int totalK = NTOK * (KVDIM / 2);
        rope_kernel<<<(totalK + 255) / 256, 256>>>(Kb, KVDIM);
    }

    // Attention (fp32)
    {
        cudaFuncSetAttribute(attention_kernel,
                             cudaFuncAttributeMaxDynamicSharedMemorySize,
                             ATTN_SMEM_BYTES);
        dim3 grid(SEQ / 64, BATCH * NHEAD);
        attention_kernel<<<grid, 256, ATTN_SMEM_BYTES>>>(Qb, Kb, Vb, Ob);
    }

    // Output projection (tf32 tensor cores)
    {
        dim3 grid(DMODEL / 128, NTOK / 128);
        tf32_gemm_bias_kernel<<<grid, 256>>>(Ob, Wo, bo, out, NTOK, DMODEL, DMODEL);
    }
}

// round 10
// speedup vs baseline: 5.5466x; 2.4616x over previous
#include <cuda_runtime.h>
#include <cuda_bf16.h>
#include <math.h>

// Problem constants
#define BATCH   2
#define SEQ     1024
#define DMODEL  2048
#define NHEAD   32
#define NKVHEAD 8
#define DK      64
#define KVDIM   (NKVHEAD * DK)   // 512
#define NTOK    (BATCH * SEQ)    // 2048

// ---------------------------------------------------------------------------
// Scratch buffers
// ---------------------------------------------------------------------------
__device__ float g_Q[NTOK * DMODEL];   // 16 MB
__device__ float g_K[NTOK * KVDIM];    //  4 MB
__device__ float g_V[NTOK * KVDIM];    //  4 MB
__device__ float g_O[NTOK * DMODEL];   // 16 MB

// ---------------------------------------------------------------------------
// tf32 / async helpers
// ---------------------------------------------------------------------------
__device__ __forceinline__ float to_tf32(float x)
{
    unsigned u;
    asm volatile("cvt.rna.tf32.f32 %0, %1;\n" : "=r"(u) : "f"(x));
    return __uint_as_float(u);
}

__device__ __forceinline__ void mma_tf32_16x8x8(float d[4],
                                                const float a[4],
                                                const float b[2])
{
    asm volatile(
        "mma.sync.aligned.m16n8k8.row.col.f32.tf32.tf32.f32 "
        "{%0,%1,%2,%3}, {%4,%5,%6,%7}, {%8,%9}, {%0,%1,%2,%3};\n"
        : "+f"(d[0]), "+f"(d[1]), "+f"(d[2]), "+f"(d[3])
        : "r"(__float_as_uint(a[0])), "r"(__float_as_uint(a[1])),
          "r"(__float_as_uint(a[2])), "r"(__float_as_uint(a[3])),
          "r"(__float_as_uint(b[0])), "r"(__float_as_uint(b[1])));
}

__device__ __forceinline__ void cp_async16(void* smem_dst, const void* gmem_src)
{
    unsigned s = (unsigned)__cvta_generic_to_shared(smem_dst);
    asm volatile("cp.async.cg.shared.global [%0], [%1], 16;\n"
                 :: "r"(s), "l"(gmem_src));
}
__device__ __forceinline__ void cp_commit()
{
    asm volatile("cp.async.commit_group;\n");
}
template <int N>
__device__ __forceinline__ void cp_wait()
{
    asm volatile("cp.async.wait_group %0;\n" :: "n"(N));
}

// ---------------------------------------------------------------------------
// TF32 GEMM + bias, cp.async double-buffered.
// C[M,N] = A[M,K] @ W[K,N] + bias[N].  BM=BN=128, BK=32, 256 threads.
// smem (dynamic): As[2][128][36] (m-major) + Bs[2][32][136] (k-major).
// Pitch 36 -> a-frag banks 4g+t (conflict-free); pitch 136 -> b-frag banks
// 8t+g (conflict-free).  Numerics identical to the R4-validated kernel
// (tf32 conversion moved to fragment-load time; same values, same order).
// ---------------------------------------------------------------------------
#define GEMM_AS_STRIDE (128 * 36)
#define GEMM_BS_STRIDE (32 * 136)
#define GEMM_SMEM_BYTES ((2 * GEMM_AS_STRIDE + 2 * GEMM_BS_STRIDE) * 4)  // 71680

__device__ __forceinline__ void gemm_issue_tile(const float* __restrict__ A,
                                                const float* __restrict__ W,
                                                float* Ab, float* Bb,
                                                int bm, int bn, int k0,
                                                int N, int K, int tid)
{
#pragma unroll
    for (int t = 0; t < 4; t++) {
        int id = tid + t * 256;          // 0..1023
        int r  = id >> 3;                // 0..127
        int c4 = id & 7;                 // 0..7
        cp_async16(&Ab[r * 36 + c4 * 4],
                   &A[(size_t)(bm + r) * K + k0 + c4 * 4]);
    }
#pragma unroll
    for (int t = 0; t < 4; t++) {
        int id = tid + t * 256;
        int r  = id >> 5;                // 0..31 (k row)
        int c4 = id & 31;                // 0..31 (n/4)
        cp_async16(&Bb[r * 136 + c4 * 4],
                   &W[(size_t)(k0 + r) * N + bn + c4 * 4]);
    }
}

__global__ __launch_bounds__(256, 2)
void tf32_gemm_bias_kernel(const float* __restrict__ A,
                           const float* __restrict__ W,
                           const float* __restrict__ bias,
                           float* __restrict__ C,
                           int M, int N, int K)
{
    extern __shared__ float gs[];
    float* As = gs;                          // [2][128][36]
    float* Bs = gs + 2 * GEMM_AS_STRIDE;     // [2][32][136]

    const int tid  = threadIdx.x;
    const int warp = tid >> 5;
    const int lane = tid & 31;
    const int wm   = warp & 3;
    const int wn   = warp >> 2;
    const int grp  = lane >> 2;
    const int tig  = lane & 3;

    const int bm = blockIdx.y * 128;
    const int bn = blockIdx.x * 128;

    float d[2][8][4];
#pragma unroll
    for (int mt = 0; mt < 2; mt++)
#pragma unroll
        for (int nt = 0; nt < 8; nt++)
#pragma unroll
            for (int i = 0; i < 4; i++) d[mt][nt][i] = 0.f;

    const int ntiles = K >> 5;

    gemm_issue_tile(A, W, As, Bs, bm, bn, 0, N, K, tid);
    cp_commit();

    for (int t = 0; t < ntiles; t++) {
        const int buf = t & 1;
        if (t + 1 < ntiles) {
            gemm_issue_tile(A, W,
                            As + (buf ^ 1) * GEMM_AS_STRIDE,
                            Bs + (buf ^ 1) * GEMM_BS_STRIDE,
                            bm, bn, (t + 1) << 5, N, K, tid);
            cp_commit();
            cp_wait<1>();
        } else {
            cp_wait<0>();
        }
        __syncthreads();

        const float* Ab = As + buf * GEMM_AS_STRIDE;
        const float* Bb = Bs + buf * GEMM_BS_STRIDE;

#pragma unroll
        for (int ks = 0; ks < 4; ks++) {
            const int kb = ks * 8;
            float a[2][4];
#pragma unroll
            for (int mt = 0; mt < 2; mt++) {
                int row = wm * 32 + mt * 16 + grp;
                a[mt][0] = to_tf32(Ab[row * 36       + kb + tig]);
                a[mt][1] = to_tf32(Ab[(row + 8) * 36 + kb + tig]);
                a[mt][2] = to_tf32(Ab[row * 36       + kb + tig + 4]);
                a[mt][3] = to_tf32(Ab[(row + 8) * 36 + kb + tig + 4]);
            }
#pragma unroll
            for (int nt = 0; nt < 8; nt++) {
                float b[2];
                int col = wn * 64 + nt * 8 + grp;
                b[0] = to_tf32(Bb[(kb + tig) * 136     + col]);
                b[1] = to_tf32(Bb[(kb + tig + 4) * 136 + col]);
#pragma unroll
                for (int mt = 0; mt < 2; mt++)
                    mma_tf32_16x8x8(d[mt][nt], a[mt], b);
            }
        }
        __syncthreads();
    }

    // Epilogue: bias + store
#pragma unroll
    for (int mt = 0; mt < 2; mt++) {
        int row0 = bm + wm * 32 + mt * 16 + grp;
#pragma unroll
        for (int nt = 0; nt < 8; nt++) {
            int col = bn + wn * 64 + nt * 8 + tig * 2;
            float2 bv = *(const float2*)&bias[col];
            float2 o0, o1;
            o0.x = d[mt][nt][0] + bv.x;  o0.y = d[mt][nt][1] + bv.y;
            o1.x = d[mt][nt][2] + bv.x;  o1.y = d[mt][nt][3] + bv.y;
            *(float2*)&C[(size_t)row0 * N + col]       = o0;
            *(float2*)&C[(size_t)(row0 + 8) * N + col] = o1;
        }
    }
}

// ---------------------------------------------------------------------------
// RoPE (in-place).
// ---------------------------------------------------------------------------
__global__ void rope_kernel(float* __restrict__ T, int ncols)
{
    int idx = blockIdx.x * blockDim.x + threadIdx.x;
    int npairs_row = ncols >> 1;
    int total = NTOK * npairs_row;
    if (idx >= total) return;
    int t = idx / npairs_row;
    int p = idx - t * npairs_row;
    int i = p & 31;
    int pos = t & (SEQ - 1);

    float inv = __powf(10000.0f, -(float)i / 32.0f);
    float ang = (float)pos * inv;
    float s, c;
    sincosf(ang, &s, &c);

    float* base = T + (size_t)t * ncols + 2 * p;
    float e = base[0];
    float o = base[1];
    base[0] = e * c - o * s;
    base[1] = e * s + o * c;
}

// ---------------------------------------------------------------------------
// Flash attention via tf32 MMA (causal, GQA).
// One block per (q_tile of 128 rows, b*h). 8 warps; each warp owns 16 q rows.
// smem: Ks[64][68] Vs[64][68] Ps[128][68]  = 69632 B dynamic.
// ---------------------------------------------------------------------------
#define ATTN_SMEM_BYTES ((64*68 + 64*68 + 128*68) * 4)

__global__ __launch_bounds__(256, 2)
void attention_mma_kernel(const float* __restrict__ Q,
                          const float* __restrict__ K,
                          const float* __restrict__ V,
                          float* __restrict__ O)
{
    extern __shared__ float sm[];
    float* Ks = sm;                 // [64][68]
    float* Vs = Ks + 64 * 68;       // [64][68]
    float* Ps = Vs + 64 * 68;       // [128][68]

    const int tid  = threadIdx.x;
    const int warp = tid >> 5;
    const int lane = tid & 31;
    const int grp  = lane >> 2;     // 0..7
    const int tig  = lane & 3;      // 0..3

    const int qt = blockIdx.x;      // 0..7  (128 q rows each)
    const int bh = blockIdx.y;      // 0..63
    const int b  = bh >> 5;
    const int h  = bh & 31;
    const int g  = h >> 2;

    const float* Qbase = Q + (size_t)(b * SEQ) * DMODEL + h * DK;
    const float* Kbase = K + (size_t)(b * SEQ) * KVDIM + g * DK;
    const float* Vbase = V + (size_t)(b * SEQ) * KVDIM + g * DK;
    float*       Obase = O + (size_t)(b * SEQ) * DMODEL + h * DK;

    const int q0 = qt * 128 + warp * 16;

    // Q fragments in registers (scaled by 1/sqrt(dk), tf32)
    float qf[8][4];
    {
        const float* r0p = Qbase + (size_t)(q0 + grp) * DMODEL;
        const float* r1p = Qbase + (size_t)(q0 + grp + 8) * DMODEL;
#pragma unroll
        for (int ks = 0; ks < 8; ks++) {
            int d0 = ks * 8 + tig;
            qf[ks][0] = to_tf32(r0p[d0]     * 0.125f);
            qf[ks][1] = to_tf32(r1p[d0]     * 0.125f);
            qf[ks][2] = to_tf32(r0p[d0 + 4] * 0.125f);
            qf[ks][3] = to_tf32(r1p[d0 + 4] * 0.125f);
        }
    }

    float o[8][4];
#pragma unroll
    for (int nt = 0; nt < 8; nt++)
#pragma unroll
        for (int i = 0; i < 4; i++) o[nt][i] = 0.f;

    float m0 = -1e30f, m1 = -1e30f, l0 = 0.f, l1 = 0.f;

    const int jt_max = 2 * qt + 1;
    for (int jt = 0; jt <= jt_max; jt++) {
#pragma unroll
        for (int t = 0; t < 4; t++) {
            int id = tid + t * 256;
            int r  = id >> 4;
            int c4 = id & 15;
            const float4 kv = *(const float4*)&Kbase[(size_t)(jt * 64 + r) * KVDIM + c4 * 4];
            float* kd = &Ks[r * 68 + c4 * 4];
            kd[0] = to_tf32(kv.x); kd[1] = to_tf32(kv.y);
            kd[2] = to_tf32(kv.z); kd[3] = to_tf32(kv.w);
            const float4 vv = *(const float4*)&Vbase[(size_t)(jt * 64 + r) * KVDIM + c4 * 4];
            float* vd = &Vs[r * 68 + c4 * 4];
            vd[0] = to_tf32(vv.x); vd[1] = to_tf32(vv.y);
            vd[2] = to_tf32(vv.z); vd[3] = to_tf32(vv.w);
        }
        __syncthreads();

        // S = Q K^T
        float s[8][4];
#pragma unroll
        for (int nt = 0; nt < 8; nt++) {
            s[nt][0] = 0.f; s[nt][1] = 0.f; s[nt][2] = 0.f; s[nt][3] = 0.f;
#pragma unroll
            for (int ks = 0; ks < 8; ks++) {
                float bf[2];
                const float* kr = &Ks[(nt * 8 + grp) * 68 + ks * 8 + tig];
                bf[0] = kr[0];
                bf[1] = kr[4];
                mma_tf32_16x8x8(s[nt], qf[ks], bf);
            }
        }

        // Causal mask
        if (jt >= 2 * qt) {
            const int r0g = q0 + grp;
            const int r1g = r0g + 8;
#pragma unroll
            for (int nt = 0; nt < 8; nt++) {
                int c = jt * 64 + nt * 8 + tig * 2;
                if (c     > r0g) s[nt][0] = -1e30f;
                if (c + 1 > r0g) s[nt][1] = -1e30f;
                if (c     > r1g) s[nt][2] = -1e30f;
                if (c + 1 > r1g) s[nt][3] = -1e30f;
            }
        }

        // Online softmax
        float ml0 = -1e30f, ml1 = -1e30f;
#pragma unroll
        for (int nt = 0; nt < 8; nt++) {
            ml0 = fmaxf(ml0, fmaxf(s[nt][0], s[nt][1]));
            ml1 = fmaxf(ml1, fmaxf(s[nt][2], s[nt][3]));
        }
        ml0 = fmaxf(ml0, __shfl_xor_sync(0xffffffffu, ml0, 1));
        ml0 = fmaxf(ml0, __shfl_xor_sync(0xffffffffu, ml0, 2));
        ml1 = fmaxf(ml1, __shfl_xor_sync(0xffffffffu, ml1, 1));
        ml1 = fmaxf(ml1, __shfl_xor_sync(0xffffffffu, ml1, 2));

        const float mn0 = fmaxf(m0, ml0);
        const float mn1 = fmaxf(m1, ml1);
        const float sc0 = __expf(m0 - mn0);
        const float sc1 = __expf(m1 - mn1);
        m0 = mn0; m1 = mn1;

        float ls0 = 0.f, ls1 = 0.f;
        float* pr0 = &Ps[(warp * 16 + grp) * 68 + tig * 2];
        float* pr1 = &Ps[(warp * 16 + grp + 8) * 68 + tig * 2];
#pragma unroll
        for (int nt = 0; nt < 8; nt++) {
            float p0 = __expf(s[nt][0] - mn0);
            float p1 = __expf(s[nt][1] - mn0);
            float p2 = __expf(s[nt][2] - mn1);
            float p3 = __expf(s[nt][3] - mn1);
            ls0 += p0 + p1;
            ls1 += p2 + p3;
            *(float2*)&pr0[nt * 8] = make_float2(to_tf32(p0), to_tf32(p1));
            *(float2*)&pr1[nt * 8] = make_float2(to_tf32(p2), to_tf32(p3));
            o[nt][0] *= sc0; o[nt][1] *= sc0;
            o[nt][2] *= sc1; o[nt][3] *= sc1;
        }
        ls0 += __shfl_xor_sync(0xffffffffu, ls0, 1);
        ls0 += __shfl_xor_sync(0xffffffffu, ls0, 2);
        ls1 += __shfl_xor_sync(0xffffffffu, ls1, 1);
        ls1 += __shfl_xor_sync(0xffffffffu, ls1, 2);
        l0 = l0 * sc0 + ls0;
        l1 = l1 * sc1 + ls1;
        __syncwarp();

        // O += P @ V
#pragma unroll
        for (int ks = 0; ks < 8; ks++) {
            float a[4];
            const float* p0p = &Ps[(warp * 16 + grp) * 68 + ks * 8 + tig];
            const float* p1p = &Ps[(warp * 16 + grp + 8) * 68 + ks * 8 + tig];
            a[0] = p0p[0];
            a[1] = p1p[0];
            a[2] = p0p[4];
            a[3] = p1p[4];
#pragma unroll
            for (int nt = 0; nt < 8; nt++) {
                float bf[2];
                const float* vp = &Vs[(ks * 8 + tig) * 68 + nt * 8 + grp];
                bf[0] = vp[0];
                bf[1] = vp[4 * 68];
                mma_tf32_16x8x8(o[nt], a, bf);
            }
        }
        __syncthreads();
    }

    // Normalize and store
    const float linv0 = 1.0f / l0;
    const float linv1 = 1.0f / l1;
    float* o0p = Obase + (size_t)(q0 + grp) * DMODEL;
    float* o1p = Obase + (size_t)(q0 + grp + 8) * DMODEL;
#pragma unroll
    for (int nt = 0; nt < 8; nt++) {
        int c = nt * 8 + tig * 2;
        *(float2*)&o0p[c] = make_float2(o[nt][0] * linv0, o[nt][1] * linv0);
        *(float2*)&o1p[c] = make_float2(o[nt][2] * linv1, o[nt][3] * linv1);
    }
}

// ---------------------------------------------------------------------------
// Launch
// ---------------------------------------------------------------------------
extern "C" void kernel_launch(void* const* d_in, const int* in_sizes, int n_in,
                              void* d_out, int out_size)
{
    const float* x  = (const float*)d_in[0];
    const float* Wq = (const float*)d_in[1];
    const float* bq = (const float*)d_in[2];
    const float* Wk = (const float*)d_in[3];
    const float* bk = (const float*)d_in[4];
    const float* Wv = (const float*)d_in[5];
    const float* bv = (const float*)d_in[6];
    const float* Wo = (const float*)d_in[7];
    const float* bo = (const float*)d_in[8];
    float* out = (float*)d_out;

    float *Qb, *Kb, *Vb, *Ob;
    cudaGetSymbolAddress((void**)&Qb, g_Q);
    cudaGetSymbolAddress((void**)&Kb, g_K);
    cudaGetSymbolAddress((void**)&Vb, g_V);
    cudaGetSymbolAddress((void**)&Ob, g_O);

    cudaFuncSetAttribute(tf32_gemm_bias_kernel,
                         cudaFuncAttributeMaxDynamicSharedMemorySize,
                         GEMM_SMEM_BYTES);
    cudaFuncSetAttribute(attention_mma_kernel,
                         cudaFuncAttributeMaxDynamicSharedMemorySize,
                         ATTN_SMEM_BYTES);

    // QKV projections (tf32 tensor cores, cp.async double-buffered)
    {
        dim3 grid(DMODEL / 128, NTOK / 128);
        tf32_gemm_bias_kernel<<<grid, 256, GEMM_SMEM_BYTES>>>(x, Wq, bq, Qb, NTOK, DMODEL, DMODEL);
    }
    {
        dim3 grid(KVDIM / 128, NTOK / 128);
        tf32_gemm_bias_kernel<<<grid, 256, GEMM_SMEM_BYTES>>>(x, Wk, bk, Kb, NTOK, KVDIM, DMODEL);
        tf32_gemm_bias_kernel<<<grid, 256, GEMM_SMEM_BYTES>>>(x, Wv, bv, Vb, NTOK, KVDIM, DMODEL);
    }

    // RoPE on Q and K
    {
        int totalQ = NTOK * (DMODEL / 2);
        rope_kernel<<<(totalQ + 255) / 256, 256>>>(Qb, DMODEL);
        int totalK = NTOK * (KVDIM / 2);
        rope_kernel<<<(totalK + 255) / 256, 256>>>(Kb, KVDIM);
    }

    // Attention (tf32 MMA)
    {
        dim3 grid(SEQ / 128, BATCH * NHEAD);
        attention_mma_kernel<<<grid, 256, ATTN_SMEM_BYTES>>>(Qb, Kb, Vb, Ob);
    }

    // Output projection (tf32 tensor cores)
    {
        dim3 grid(DMODEL / 128, NTOK / 128);
        tf32_gemm_bias_kernel<<<grid, 256, GEMM_SMEM_BYTES>>>(Ob, Wo, bo, out, NTOK, DMODEL, DMODEL);
    }
}